// round 2
// baseline (speedup 1.0000x reference)
#include <cuda_runtime.h>
#include <math.h>

// Problem constants
#define BB   32
#define LL   65536          // T*K
#define CC   6
#define CS   2048           // sequence chunk per block
#define NC   (LL / CS)      // 32 chunks per (batch)
#define PP   128            // positions per tile
#define TPB  (PP * CC)      // 768 threads
#define TILES (CS / PP)     // 16 tiles per block

// Scratch (device globals — no allocation allowed)
__device__ float g_W[BB * NC * CC];   // chunk weighted partial sums
__device__ float g_E[BB * NC * CC];   // exclusive prefix of g_W over chunks
__device__ float g_temp[LL];          // temperature curve

__device__ __forceinline__ float ch_std0(int c)  { return (c < 3) ? 0.2f   : 0.015f; }
__device__ __forceinline__ float ch_noise(int c) { return (c < 3) ? 0.1f   : 0.01f;  }
__device__ __forceinline__ float ch_tcoef(int c) { return (c < 3) ? 0.001f : 0.01f;  }

// ---------------------------------------------------------------------------
// Temperature table: temp[t] = 20 + 5*sin(2*pi*t/(L-1)) + 2*t/(L-1)
// ---------------------------------------------------------------------------
__global__ void temp_kernel() {
    int t = blockIdx.x * blockDim.x + threadIdx.x;
    if (t < LL) {
        float tt = (float)t / (float)(LL - 1);
        g_temp[t] = 20.0f + 5.0f * sinf(6.283185307179586f * tt) + 2.0f * tt;
    }
}

// ---------------------------------------------------------------------------
// Phase A: per (b, chunk) weighted partial sums
//   W[b,k,c] = sum_{j in [k*CS, (k+1)*CS)} w_j,  w_j = walk[j-1]*ds*a^{-j} (w_0 = 0)
// ---------------------------------------------------------------------------
__global__ __launch_bounds__(TPB) void chunk_sum_kernel(const float* __restrict__ walk) {
    const int bx = blockIdx.x;
    const int b = bx / NC, k = bx % NC;
    const int tid = threadIdx.x;
    const int c = tid % CC, p = tid / CC;

    const double la = log(1.0 - 1e-5);          // ln(a), a = 1 - theta*dt
    const int j0 = k * CS + p;
    float ainv = (float)exp(-(double)j0 * la);  // a^{-j0}
    const float AINV_STEP = (float)exp(-(double)PP * la);

    const float ds = ch_std0(c) * (float)(sqrt(2.0 * 0.01) * sqrt(0.001));
    const int wbase = (b * (LL - 1)) * CC + c;

    float acc = 0.0f;
    int j = j0;
    #pragma unroll
    for (int i = 0; i < TILES; ++i) {
        float x = (j >= 1) ? walk[wbase + (j - 1) * CC] : 0.0f;
        acc += x * ds * ainv;
        ainv *= AINV_STEP;
        j += PP;
    }

    __shared__ float red[TPB];
    red[tid] = acc;
    __syncthreads();
    #pragma unroll
    for (int s = TPB / 2; s >= CC; s >>= 1) {   // 384,192,96,48,24,12,6 (all mult of 6)
        if (tid < s) red[tid] += red[tid + s];
        __syncthreads();
    }
    if (tid < CC) g_W[(b * NC + k) * CC + tid] = red[tid];
}

// ---------------------------------------------------------------------------
// Phase B: exclusive prefix over chunks, per (b, c). 192 threads, 1 block.
// ---------------------------------------------------------------------------
__global__ void carry_scan_kernel() {
    int t = threadIdx.x;                 // 0..191
    if (t >= BB * CC) return;
    int b = t / CC, c = t % CC;
    float run = 0.0f;
    #pragma unroll
    for (int k = 0; k < NC; ++k) {
        g_E[(b * NC + k) * CC + c] = run;
        run += g_W[(b * NC + k) * CC + c];
    }
}

// ---------------------------------------------------------------------------
// Phase C: fused local scan + bias reconstruction + epilogue.
//   bias_t = a^t * (bias0 + E[b,k,c] + local_inclusive_prefix(w))
//   out    = imu + bias + meas*noise_std + temp[t]*tcoef
// ---------------------------------------------------------------------------
__global__ __launch_bounds__(TPB) void apply_kernel(
    const float* __restrict__ imu,
    const float* __restrict__ eps0,
    const float* __restrict__ walk,
    const float* __restrict__ meas,
    float* __restrict__ out)
{
    __shared__ float buf[2][TPB];

    const int bx = blockIdx.x;
    const int b = bx / NC, k = bx % NC;
    const int tid = threadIdx.x;
    const int c = tid % CC, p = tid / CC;

    const double la = log(1.0 - 1e-5);
    const int t0 = k * CS + p;
    float ainv = (float)exp(-(double)t0 * la);      // a^{-t}
    float apos = (float)exp((double)t0 * la);       // a^{+t}
    const float AINV_STEP = (float)exp(-(double)PP * la);
    const float APOS_STEP = (float)exp((double)PP * la);

    const float ds = ch_std0(c) * (float)(sqrt(2.0 * 0.01) * sqrt(0.001));
    const float ns = ch_noise(c);
    const float tc = ch_tcoef(c);

    const float bias0 = eps0[b * CC + c] * ch_std0(c);
    float carry = bias0 + g_E[(b * NC + k) * CC + c];

    const int lbase = (b * LL) * CC + c;
    const int wbase = (b * (LL - 1)) * CC + c;

    int t = t0;
    for (int i = 0; i < TILES; ++i) {
        const int oidx = lbase + t * CC;
        // issue all independent global loads up front
        float w  = (t >= 1) ? walk[wbase + (t - 1) * CC] * ds * ainv : 0.0f;
        float vi = imu[oidx];
        float vm = meas[oidx];
        float vt = g_temp[t];

        buf[0][tid] = w;
        __syncthreads();

        // Hillis-Steele inclusive scan over p (per channel), 7 steps, double-buffered
        #pragma unroll
        for (int s = 0; s < 7; ++s) {
            const int d = 1 << s;
            float v = buf[s & 1][tid];
            if (p >= d) v += buf[s & 1][tid - CC * d];
            buf[(s + 1) & 1][tid] = v;
            __syncthreads();
        }
        // 7 steps (odd) -> result in buf[1]
        float incl = buf[1][tid];
        float last = buf[1][(PP - 1) * CC + c];

        float bias = apos * (carry + incl);
        carry += last;

        out[oidx] = vi + bias + vm * ns + vt * tc;

        ainv *= AINV_STEP;
        apos *= APOS_STEP;
        t += PP;
        // no trailing barrier needed: next tile writes buf[0]; this tile's final
        // reads target buf[1], and the post-write barrier orders buf[1] reuse.
    }
}

// ---------------------------------------------------------------------------
extern "C" void kernel_launch(void* const* d_in, const int* in_sizes, int n_in,
                              void* d_out, int out_size) {
    const float* imu  = (const float*)d_in[0];   // [32, 4096, 16, 6]
    const float* eps0 = (const float*)d_in[1];   // [32, 6]
    const float* walk = (const float*)d_in[2];   // [32, 65535, 6]
    const float* meas = (const float*)d_in[3];   // [32, 65536, 6]
    float* out = (float*)d_out;

    temp_kernel<<<(LL + 1023) / 1024, 1024>>>();
    chunk_sum_kernel<<<BB * NC, TPB>>>(walk);
    carry_scan_kernel<<<1, BB * CC>>>();
    apply_kernel<<<BB * NC, TPB>>>(imu, eps0, walk, meas, out);
}

// round 3
// speedup vs baseline: 5.2028x; 5.2028x over previous
#include <cuda_runtime.h>
#include <math.h>

// Problem constants
#define BB   32
#define LL   65536          // T*K
#define CC   6
#define CS   4096           // sequence chunk per block
#define NC   (LL / CS)      // 16 chunks per batch
#define TPB  768            // 24 warps
#define PTILE 512           // positions per tile in apply
#define NTILE (CS / PTILE)  // 8 tiles per block

// ln(a) magnitude, a = 1 - theta*dt = 0.99999 ;  a^{-t} = exp(t*LPc)
#define LPc 1.0000050000333335e-05f
// sqrt(2*theta*dt) = sqrt(2e-5)
#define SQc 4.4721359549995794e-03f

__device__ float g_W[BB * NC * CC];   // chunk weighted partial sums
__device__ float g_E[BB * NC * CC];   // exclusive prefix over chunks
__device__ float g_temp[LL];          // temperature curve

__device__ __forceinline__ float ch_std0(int c)  { return (c < 3) ? 0.2f   : 0.015f; }
__device__ __forceinline__ float ch_noise(int c) { return (c < 3) ? 0.1f   : 0.01f;  }
__device__ __forceinline__ float ch_tcoef(int c) { return (c < 3) ? 0.001f : 0.01f;  }

// ---------------------------------------------------------------------------
__global__ void temp_kernel() {
    int t = blockIdx.x * blockDim.x + threadIdx.x;
    if (t < LL) {
        float tt = (float)t / (float)(LL - 1);
        g_temp[t] = 20.0f + 5.0f * sinf(6.283185307179586f * tt) + 2.0f * tt;
    }
}

// ---------------------------------------------------------------------------
// Phase A: W[b,k,c] = sum_{j in chunk k} walk[j-1]*ds*a^{-j}   (w_0 = 0)
// ---------------------------------------------------------------------------
__global__ __launch_bounds__(TPB) void chunk_sum_kernel(const float* __restrict__ walk) {
    const int bx = blockIdx.x;
    const int b = bx / NC, k = bx % NC;
    const int tid = threadIdx.x;
    const int c = tid % CC, p = tid / CC;       // p in 0..127

    const int j0 = k * CS + p;
    float ainv = expf((float)j0 * LPc);         // a^{-j0}
    const float STEP = expf(128.0f * LPc);      // a^{-128}
    const float ds = ch_std0(c) * SQc;
    const float* wp = walk + (size_t)b * (LL - 1) * CC + c;

    float acc = 0.0f;
    int j = j0;
    #pragma unroll
    for (int i = 0; i < CS / 128; ++i) {
        float x = (j >= 1) ? wp[(size_t)(j - 1) * CC] : 0.0f;
        acc += x * ds * ainv;
        ainv *= STEP;
        j += 128;
    }

    __shared__ float red[TPB];
    red[tid] = acc;
    __syncthreads();
    #pragma unroll
    for (int s = TPB / 2; s >= CC; s >>= 1) {   // 384..6, all multiples of 6
        if (tid < s) red[tid] += red[tid + s];
        __syncthreads();
    }
    if (tid < CC) g_W[(b * NC + k) * CC + tid] = red[tid];
}

// ---------------------------------------------------------------------------
// Phase B: exclusive prefix over NC chunks per (b,c)
// ---------------------------------------------------------------------------
__global__ void carry_scan_kernel() {
    int t = threadIdx.x;
    if (t >= BB * CC) return;
    int b = t / CC, c = t % CC;
    float run = 0.0f;
    #pragma unroll
    for (int k = 0; k < NC; ++k) {
        g_E[(b * NC + k) * CC + c] = run;
        run += g_W[(b * NC + k) * CC + c];
    }
}

// ---------------------------------------------------------------------------
// Phase C: transpose-through-smem + warp-shuffle scan + fused epilogue.
// Warp w owns channel c = w%6, position group g = w/6 (128 pos per group).
// Lane owns 4 contiguous positions -> one LDS.128 / STS.128, conflict-free.
// ---------------------------------------------------------------------------
__global__ __launch_bounds__(TPB) void apply_kernel(
    const float* __restrict__ imu,
    const float* __restrict__ eps0,
    const float* __restrict__ walk,
    const float* __restrict__ meas,
    float* __restrict__ out)
{
    __shared__ __align__(16) float sm[2][CC * PTILE];   // [c][p], double buffered
    __shared__ float gsum[4 * CC];                      // per-group channel sums

    const int bx = blockIdx.x;
    const int b = bx / NC, k = bx % NC;
    const int tid = threadIdx.x;
    const int w = tid >> 5, l = tid & 31;
    const int c = w % CC, g = w / CC;        // compute role
    const int p0 = g * 128 + l * 4;          // first tile-local position
    const int cstart = k * CS;

    // flat-element role (load scatter + epilogue): element f = tid*4 + i
    int pe[4], ce[4];
    float nse[4], tce[4];
    #pragma unroll
    for (int i = 0; i < 4; ++i) {
        int f = tid * 4 + i;
        pe[i] = f / 6; ce[i] = f % 6;
        nse[i] = ch_noise(ce[i]); tce[i] = ch_tcoef(ce[i]);
    }

    const float ds = ch_std0(c) * SQc;
    const float ai1 = expf(LPc), ai2 = ai1 * ai1, ai3 = ai2 * ai1;
    const float ds0 = ds, ds1 = ds * ai1, ds2 = ds * ai2, ds3 = ds * ai3;
    const float ap1 = expf(-LPc), ap2 = ap1 * ap1, ap3 = ap2 * ap1;
    const float AIT = expf(512.0f * LPc), APT = expf(-512.0f * LPc);

    const int t0 = cstart + p0;
    float ainv = expf((float)t0 * LPc);      // a^{-t0}
    float apos = expf(-(float)t0 * LPc);     // a^{+t0}

    float carry = eps0[b * CC + c] * ch_std0(c) + g_E[(b * NC + k) * CC + c];

    for (int it = 0; it < NTILE; ++it) {
        const int tstart = cstart + it * PTILE;
        float* smb = sm[it & 1];

        // --- scatter load: coalesced LDG, transpose into [c][p] ---
        const float* wp = walk + ((size_t)b * (LL - 1) + tstart) * CC - CC;
        #pragma unroll
        for (int i = 0; i < 4; ++i) {
            int f = tid * 4 + i;
            float v = (tstart + pe[i] >= 1) ? wp[f] : 0.0f;
            smb[ce[i] * PTILE + pe[i]] = v;
        }
        __syncthreads();

        // --- per-warp scan: serial(4) + warp shuffle scan ---
        float4 v4 = *(const float4*)&smb[c * PTILE + p0];
        float w0 = v4.x * ds0 * ainv, w1 = v4.y * ds1 * ainv;
        float w2 = v4.z * ds2 * ainv, w3 = v4.w * ds3 * ainv;
        float s0 = w0, s1 = s0 + w1, s2 = s1 + w2, s3 = s2 + w3;

        float sc = s3;
        #pragma unroll
        for (int d = 1; d < 32; d <<= 1) {
            float o = __shfl_up_sync(0xffffffffu, sc, d);
            if (l >= d) sc += o;
        }
        float excl = sc - s3;
        if (l == 31) gsum[g * CC + c] = sc;
        __syncthreads();

        float ge = 0.0f, tot = 0.0f;
        #pragma unroll
        for (int gg = 0; gg < 4; ++gg) {
            float x = gsum[gg * CC + c];     // broadcast read
            tot += x;
            if (gg < g) ge += x;
        }
        float base = carry + ge + excl;
        carry += tot;

        float a0 = apos, a1 = apos * ap1, a2 = apos * ap2, a3 = apos * ap3;
        float4 bo;
        bo.x = (base + s0) * a0; bo.y = (base + s1) * a1;
        bo.z = (base + s2) * a2; bo.w = (base + s3) * a3;
        *(float4*)&smb[c * PTILE + p0] = bo;     // own slots; no extra hazard
        __syncthreads();

        // --- fused epilogue: fully coalesced float4 ---
        const size_t gb = ((size_t)b * LL + tstart) * CC;
        float4 vi = *(const float4*)(imu + gb + tid * 4);
        float4 vm = *(const float4*)(meas + gb + tid * 4);
        float4 o4;
        o4.x = vi.x + smb[ce[0] * PTILE + pe[0]] + vm.x * nse[0] + g_temp[tstart + pe[0]] * tce[0];
        o4.y = vi.y + smb[ce[1] * PTILE + pe[1]] + vm.y * nse[1] + g_temp[tstart + pe[1]] * tce[1];
        o4.z = vi.z + smb[ce[2] * PTILE + pe[2]] + vm.z * nse[2] + g_temp[tstart + pe[2]] * tce[2];
        o4.w = vi.w + smb[ce[3] * PTILE + pe[3]] + vm.w * nse[3] + g_temp[tstart + pe[3]] * tce[3];
        *(float4*)(out + gb + tid * 4) = o4;

        ainv *= AIT;
        apos *= APT;
        // no tail barrier: next tile scatters into the other buffer; the three
        // barriers of the next tile order reuse of this one.
    }
}

// ---------------------------------------------------------------------------
extern "C" void kernel_launch(void* const* d_in, const int* in_sizes, int n_in,
                              void* d_out, int out_size) {
    const float* imu  = (const float*)d_in[0];   // [32, 4096, 16, 6]
    const float* eps0 = (const float*)d_in[1];   // [32, 6]
    const float* walk = (const float*)d_in[2];   // [32, 65535, 6]
    const float* meas = (const float*)d_in[3];   // [32, 65536, 6]
    float* out = (float*)d_out;

    temp_kernel<<<(LL + 1023) / 1024, 1024>>>();
    chunk_sum_kernel<<<BB * NC, TPB>>>(walk);
    carry_scan_kernel<<<1, BB * CC>>>();
    apply_kernel<<<BB * NC, TPB>>>(imu, eps0, walk, meas, out);
}

// round 4
// speedup vs baseline: 6.9058x; 1.3273x over previous
#include <cuda_runtime.h>
#include <math.h>

// Problem constants
#define BB    32
#define LL    65536          // T*K
#define CC    6
#define POSB  1024           // positions per block (one tile = one block)
#define NCH   (LL / POSB)    // 64 chunks per batch
#define TPB   512            // 16 warps; thread owns 2 positions x 6 channels
#define GRID  (BB * NCH)     // 2048 blocks

// -ln(a), a = 1 - theta*dt = 0.99999 ; a^{-t} = exp(t*LPc)
#define LPc 1.0000050000333335e-05f
// sqrt(2*theta*dt) = sqrt(2e-5)
#define SQc 4.4721359549995794e-03f

__device__ float g_W[BB * NCH * CC];  // chunk weighted partial sums
__device__ float g_E[BB * NCH * CC];  // exclusive prefix over chunks
__device__ float g_temp[LL];          // temperature curve

__device__ __forceinline__ float ch_std0(int c)  { return (c < 3) ? 0.2f   : 0.015f; }
__device__ __forceinline__ float ch_noise(int c) { return (c < 3) ? 0.1f   : 0.01f;  }
__device__ __forceinline__ float ch_tcoef(int c) { return (c < 3) ? 0.001f : 0.01f;  }

// ---------------------------------------------------------------------------
__global__ void temp_kernel() {
    int t = blockIdx.x * blockDim.x + threadIdx.x;
    if (t < LL) {
        float tt = (float)t / (float)(LL - 1);
        g_temp[t] = 20.0f + 5.0f * sinf(6.283185307179586f * tt) + 2.0f * tt;
    }
}

// ---------------------------------------------------------------------------
// Load the 12 walk floats feeding this thread's 2 positions (shifted by one
// position: w_t uses walk[t-1]; w_0 = 0). 6x float2, 8B-aligned, coalesced.
// ---------------------------------------------------------------------------
__device__ __forceinline__ void load_walk12(const float* __restrict__ walk,
                                            int b, int p0, float wv[12]) {
    if (p0 == 0) {
        const float* w2 = walk + (size_t)b * (LL - 1) * CC;
        #pragma unroll
        for (int i = 0; i < 6; ++i) wv[i] = 0.0f;
        #pragma unroll
        for (int i = 0; i < 3; ++i) {
            float2 v = *(const float2*)(w2 + 2 * i);
            wv[6 + 2 * i] = v.x; wv[7 + 2 * i] = v.y;
        }
    } else {
        const float* wp = walk + (size_t)b * (LL - 1) * CC + (size_t)(p0 - 1) * CC;
        #pragma unroll
        for (int i = 0; i < 6; ++i) {
            float2 v = *(const float2*)(wp + 2 * i);
            wv[2 * i] = v.x; wv[2 * i + 1] = v.y;
        }
    }
}

// ---------------------------------------------------------------------------
// Phase A: W[b,k,c] = sum over chunk of walk[t-1]*ds_c*a^{-t}
// ---------------------------------------------------------------------------
__global__ __launch_bounds__(TPB) void chunk_sum_kernel(const float* __restrict__ walk) {
    __shared__ float wsum[16][CC];
    const int bx = blockIdx.x;
    const int b = bx >> 6, k = bx & (NCH - 1);
    const int tid = threadIdx.x;
    const int w = tid >> 5, l = tid & 31;
    const int p0 = k * POSB + tid * 2;

    float wv[12];
    load_walk12(walk, b, p0, wv);

    const float ainv0 = expf((float)p0 * LPc);
    const float ainv1 = ainv0 * (1.0f + LPc);   // a^{-1} = e^{LPc}, 1st order exact to 5e-11

    float t6[CC];
    #pragma unroll
    for (int c = 0; c < CC; ++c) {
        float ds = ch_std0(c) * SQc;
        t6[c] = wv[c] * ds * ainv0 + wv[6 + c] * ds * ainv1;
    }
    #pragma unroll
    for (int d = 16; d >= 1; d >>= 1)
        #pragma unroll
        for (int c = 0; c < CC; ++c)
            t6[c] += __shfl_down_sync(0xffffffffu, t6[c], d);
    if (l == 0)
        #pragma unroll
        for (int c = 0; c < CC; ++c) wsum[w][c] = t6[c];
    __syncthreads();
    if (w == 0 && l < 16) {
        float v[CC];
        #pragma unroll
        for (int c = 0; c < CC; ++c) v[c] = wsum[l][c];
        #pragma unroll
        for (int d = 8; d >= 1; d >>= 1)
            #pragma unroll
            for (int c = 0; c < CC; ++c)
                v[c] += __shfl_down_sync(0x0000ffffu, v[c], d);
        if (l == 0)
            #pragma unroll
            for (int c = 0; c < CC; ++c) g_W[(b * NCH + k) * CC + c] = v[c];
    }
}

// ---------------------------------------------------------------------------
// Phase B: exclusive prefix over NCH chunks per (b,c)
// ---------------------------------------------------------------------------
__global__ void carry_scan_kernel() {
    int t = threadIdx.x;
    if (t >= BB * CC) return;
    int b = t / CC, c = t % CC;
    float run = 0.0f;
    #pragma unroll 8
    for (int k = 0; k < NCH; ++k) {
        g_E[(b * NCH + k) * CC + c] = run;
        run += g_W[(b * NCH + k) * CC + c];
    }
}

// ---------------------------------------------------------------------------
// Phase C: register-resident per-channel scan + fused epilogue.
// Thread owns 2 complete positions; all global traffic coalesced; 2 barriers.
// ---------------------------------------------------------------------------
__global__ __launch_bounds__(TPB, 2) void apply_kernel(
    const float* __restrict__ imu,
    const float* __restrict__ eps0,
    const float* __restrict__ walk,
    const float* __restrict__ meas,
    float* __restrict__ out)
{
    __shared__ float wsum[16][CC];
    __shared__ float wexc[16][CC];

    const int bx = blockIdx.x;
    const int b = bx >> 6, k = bx & (NCH - 1);
    const int tid = threadIdx.x;
    const int w = tid >> 5, l = tid & 31;
    const int tstart = k * POSB;
    const int p0 = tstart + tid * 2;

    float wv[12];
    load_walk12(walk, b, p0, wv);

    const float ainv0 = expf((float)p0 * LPc);
    const float ainv1 = ainv0 * (1.0f + LPc);
    const float apos0 = expf(-(float)p0 * LPc);
    const float apos1 = apos0 * (1.0f - LPc);

    float w0[CC], w1[CC], t6[CC];
    #pragma unroll
    for (int c = 0; c < CC; ++c) {
        float ds = ch_std0(c) * SQc;
        w0[c] = wv[c] * ds * ainv0;
        w1[c] = wv[6 + c] * ds * ainv1;
        t6[c] = w0[c] + w1[c];
    }

    // warp-inclusive scan per channel (6 parallel chains)
    float incl[CC];
    #pragma unroll
    for (int c = 0; c < CC; ++c) incl[c] = t6[c];
    #pragma unroll
    for (int d = 1; d < 32; d <<= 1)
        #pragma unroll
        for (int c = 0; c < CC; ++c) {
            float o = __shfl_up_sync(0xffffffffu, incl[c], d);
            if (l >= d) incl[c] += o;
        }
    if (l == 31)
        #pragma unroll
        for (int c = 0; c < CC; ++c) wsum[w][c] = incl[c];
    __syncthreads();

    // second level: warp 0 scans the 16 warp totals -> exclusive
    if (w == 0 && l < 16) {
        float v[CC], inc2[CC];
        #pragma unroll
        for (int c = 0; c < CC; ++c) { v[c] = wsum[l][c]; inc2[c] = v[c]; }
        #pragma unroll
        for (int d = 1; d < 16; d <<= 1)
            #pragma unroll
            for (int c = 0; c < CC; ++c) {
                float o = __shfl_up_sync(0x0000ffffu, inc2[c], d);
                if (l >= d) inc2[c] += o;
            }
        #pragma unroll
        for (int c = 0; c < CC; ++c) wexc[l][c] = inc2[c] - v[c];
    }
    __syncthreads();

    // bias in registers for both positions
    const int ebase = (b * NCH + k) * CC;
    float bias0[CC], bias1[CC];
    #pragma unroll
    for (int c = 0; c < CC; ++c) {
        float carry = eps0[b * CC + c] * ch_std0(c) + g_E[ebase + c];
        float base = carry + wexc[w][c] + (incl[c] - t6[c]);  // exclusive up to p0
        bias0[c] = (base + w0[c]) * apos0;
        bias1[c] = (base + w0[c] + w1[c]) * apos1;
    }

    // fused epilogue: 12 contiguous floats, 3x float4 in/out
    const size_t gb = ((size_t)b * LL + tstart) * CC + (size_t)tid * 12;
    const float tm0 = g_temp[p0], tm1 = g_temp[p0 + 1];

    float bias[12], tadd[12], ns[12];
    #pragma unroll
    for (int c = 0; c < CC; ++c) {
        bias[c] = bias0[c];      bias[6 + c] = bias1[c];
        tadd[c] = tm0 * ch_tcoef(c); tadd[6 + c] = tm1 * ch_tcoef(c);
        ns[c] = ch_noise(c);     ns[6 + c] = ch_noise(c);
    }
    #pragma unroll
    for (int q = 0; q < 3; ++q) {
        float4 vi = *(const float4*)(imu + gb + q * 4);
        float4 vm = *(const float4*)(meas + gb + q * 4);
        float4 o4;
        o4.x = vi.x + bias[q * 4 + 0] + vm.x * ns[q * 4 + 0] + tadd[q * 4 + 0];
        o4.y = vi.y + bias[q * 4 + 1] + vm.y * ns[q * 4 + 1] + tadd[q * 4 + 1];
        o4.z = vi.z + bias[q * 4 + 2] + vm.z * ns[q * 4 + 2] + tadd[q * 4 + 2];
        o4.w = vi.w + bias[q * 4 + 3] + vm.w * ns[q * 4 + 3] + tadd[q * 4 + 3];
        *(float4*)(out + gb + q * 4) = o4;
    }
}

// ---------------------------------------------------------------------------
extern "C" void kernel_launch(void* const* d_in, const int* in_sizes, int n_in,
                              void* d_out, int out_size) {
    const float* imu  = (const float*)d_in[0];   // [32, 4096, 16, 6]
    const float* eps0 = (const float*)d_in[1];   // [32, 6]
    const float* walk = (const float*)d_in[2];   // [32, 65535, 6]
    const float* meas = (const float*)d_in[3];   // [32, 65536, 6]
    float* out = (float*)d_out;

    temp_kernel<<<(LL + 1023) / 1024, 1024>>>();
    chunk_sum_kernel<<<GRID, TPB>>>(walk);
    carry_scan_kernel<<<1, BB * CC>>>();
    apply_kernel<<<GRID, TPB>>>(imu, eps0, walk, meas, out);
}